// round 12
// baseline (speedup 1.0000x reference)
#include <cuda_runtime.h>
#include <cstddef>

// 2-layer LSTM (H=20) + FC head, B=4096, T=512, D=1.
// 512-thread block = two independent 256-thread pipelines (16 seqs each),
// named barriers per pipe. Phase M: warps 0-3 gates1(t), warps 4-7 gates0(t+1).
// Phase C: all 8 warps, half-warp owns units hwm, hwm+8, hwm+16(<20).
// NEW: gate activations via MUFU.TANH (sigmoid = 0.5*tanh(x/2)+0.5; tanh(g)
// direct); tanh(c) kept exact. h stored (h,h)-duplicated u64 -> LDS.64 in M.

using u64 = unsigned long long;

__device__ __forceinline__ u64 fma2(u64 a, u64 b, u64 c) {
    u64 d;
    asm("fma.rn.f32x2 %0, %1, %2, %3;" : "=l"(d) : "l"(a), "l"(b), "l"(c));
    return d;
}
__device__ __forceinline__ u64 pk2(float lo, float hi) {
    u64 r;
    asm("mov.b64 %0, {%1, %2};" : "=l"(r) : "f"(lo), "f"(hi));
    return r;
}
__device__ __forceinline__ void up2(float& lo, float& hi, u64 v) {
    asm("mov.b64 {%0, %1}, %2;" : "=f"(lo), "=f"(hi) : "l"(v));
}
__device__ __forceinline__ float ex2_(float x) {
    float y; asm("ex2.approx.f32 %0, %1;" : "=f"(y) : "f"(x)); return y;
}
__device__ __forceinline__ float rcp_(float x) {
    float y; asm("rcp.approx.f32 %0, %1;" : "=f"(y) : "f"(x)); return y;
}
__device__ __forceinline__ float tanha_(float x) {
    float y; asm("tanh.approx.f32 %0, %1;" : "=f"(y) : "f"(x)); return y;
}

#define L2E 1.4426950408889634f

// gate sigmoid: 1 MUFU (exact identity, approx tanh)
__device__ __forceinline__ float sigm_(float x) {
    return fmaf(0.5f, tanha_(0.5f * x), 0.5f);
}
// cell-path tanh: exact-ish (2 MUFU)
__device__ __forceinline__ float tanhx_(float x) {
    return fmaf(2.0f, rcp_(1.0f + ex2_(-2.0f * L2E * x)), -1.0f);
}

// pipeline-scoped named barrier (ids 1 and 2; 0 reserved for __syncthreads)
#define PBAR(Pid) asm volatile("bar.sync %0, 256;" :: "r"((Pid) + 1) : "memory")

// pair p in [0,40): p<20 -> rows (p, 20+p) = (i,f) of unit p
//                   p>=20 -> rows (40+j, 60+j) = (g,o) of unit j=p-20
__global__ void __launch_bounds__(512, 1) lstm2_fc_kernel(
    const float* __restrict__ x,     // [B, T]
    const float* __restrict__ Wih0,  // [80, 1]
    const float* __restrict__ Whh0,  // [80, 20]
    const float* __restrict__ bih0,  // [80]
    const float* __restrict__ bhh0,  // [80]
    const float* __restrict__ Wih1,  // [80, 20]
    const float* __restrict__ Whh1,  // [80, 20]
    const float* __restrict__ bih1,  // [80]
    const float* __restrict__ bhh1,  // [80]
    const float* __restrict__ fcW,   // [1, 20]
    const float* __restrict__ fcb,   // [1]
    float* __restrict__ out,         // [B, 1]
    int Btot, int Tlen)
{
    __shared__ __align__(16) u64 w0s[40 * 20];      // pair-packed Whh0
    __shared__ __align__(16) u64 w1s[40 * 40];      // pair-packed [Wih1 | Whh1]
    __shared__ __align__(16) u64 gsh0[2 * 40 * 16]; // per-pipe layer0 gates
    __shared__ __align__(16) u64 gsh1[2 * 40 * 16]; // per-pipe layer1 gates
    __shared__ __align__(16) u64 h0s[2 * 20 * 16];  // (h,h)-dup h0, per-pipe
    __shared__ __align__(16) u64 h1s[2 * 20 * 16];  // (h,h)-dup h1, per-pipe
    __shared__ __align__(16) float xs[2 * 16 * 16]; // per-pipe 16-step x tile

    const int tid = threadIdx.x;

    // ---- pack weights (pair layout), all 512 threads ----
    for (int idx = tid; idx < 800; idx += 512) {
        int p = idx / 20, m = idx % 20;
        int j = (p < 20) ? p : (p - 20);
        int rlo = (p < 20) ? j : (40 + j);
        int rhi = rlo + 20;
        w0s[p * 20 + m] = pk2(Whh0[rlo * 20 + m], Whh0[rhi * 20 + m]);
    }
    for (int idx = tid; idx < 1600; idx += 512) {
        int p = idx / 40, mm = idx % 40;
        int j = (p < 20) ? p : (p - 20);
        int rlo = (p < 20) ? j : (40 + j);
        int rhi = rlo + 20;
        const float* mat = (mm < 20) ? Wih1 : Whh1;
        int m = (mm < 20) ? mm : (mm - 20);
        w1s[p * 40 + mm] = pk2(mat[rlo * 20 + m], mat[rhi * 20 + m]);
    }
    for (int idx = tid; idx < 640; idx += 512) { h0s[idx] = 0ull; h1s[idx] = 0ull; }

    // ---- lane / pipeline mapping ----
    const int P    = tid >> 8;          // pipeline 0/1
    const int lt   = tid & 255;         // local tid within pipeline
    const int w8   = lt >> 5;           // warp-in-pipeline 0..7
    const int lane = tid & 31;
    const int half = lane >> 4;
    const int s16  = lane & 15;         // sequence within pipeline
    const bool isG1 = (w8 < 4);         // warps 0-3: gates1 ; 4-7: gates0
    const int hwm  = ((w8 & 3) << 1) | half;   // half-warp id 0..7
    const int pb   = hwm * 5;           // first pair owned in phase M
    const int b0g  = blockIdx.x * 32;
    const int sbase = b0g + P * 16;     // first seq of this pipeline

    // per-lane pair scalars from global (tiny, one-time)
    u64 wxp[5], bp[5];
    #pragma unroll
    for (int k = 0; k < 5; ++k) {
        int pp = pb + k;
        int j = (pp < 20) ? pp : (pp - 20);
        int rlo = (pp < 20) ? j : (40 + j);
        int rhi = rlo + 20;
        wxp[k] = pk2(__ldg(&Wih0[rlo]), __ldg(&Wih0[rhi]));
        bp[k] = isG1
            ? pk2(__ldg(&bih1[rlo]) + __ldg(&bhh1[rlo]), __ldg(&bih1[rhi]) + __ldg(&bhh1[rhi]))
            : pk2(__ldg(&bih0[rlo]) + __ldg(&bhh0[rlo]), __ldg(&bih0[rhi]) + __ldg(&bhh0[rhi]));
    }

    __syncthreads();   // weights packed, h zeroed (block-wide, once)

    // pipeline-local pointers
    u64* g0 = &gsh0[P * 640];
    u64* g1 = &gsh1[P * 640];
    u64* h0 = &h0s[P * 320];
    u64* h1 = &h1s[P * 320];
    float* xt_tile = &xs[P * 256];

    // ---- stage x tile [0,16) : 256 threads, 1 elem each ----
    {
        int sq = lt & 15, tt = lt >> 4;
        int bb = sbase + sq;
        const float* xrow = x + (size_t)((bb < Btot) ? bb : (Btot - 1)) * Tlen;
        xt_tile[tt * 16 + sq] = (tt < Tlen && bb < Btot) ? __ldg(&xrow[tt]) : 0.f;
    }
    PBAR(P);

    // cell state: warps 4-7 own c0, warps 0-3 own c1; units uu = hwm + 8*jj (uu<20)
    float cs[3] = {0.f, 0.f, 0.f};

    // ---- prologue: gates0(0) = Wih0*x(0) + b0 (h0(-1)=0), G0 warps ----
    if (!isG1) {
        float x0 = xt_tile[0 * 16 + s16];
        u64 x02 = pk2(x0, x0);
        #pragma unroll
        for (int k = 0; k < 5; ++k)
            g0[(pb + k) * 16 + s16] = fma2(wxp[k], x02, bp[k]);
    }
    PBAR(P);

    #pragma unroll 1
    for (int t = 0; t < Tlen; ++t) {
        // ================= PHASE C =================
        if (!isG1 || t > 0) {
            const u64* gg = isG1 ? g1 : g0;   // cell1 reads gsh1, cell0 reads gsh0
            u64*       hd = isG1 ? h1 : h0;
            #pragma unroll
            for (int jj = 0; jj < 3; ++jj) {
                int uu = hwm + 8 * jj;
                if (uu < 20) {
                    float gi, gf, ga, go;
                    up2(gi, gf, gg[uu * 16 + s16]);
                    up2(ga, go, gg[(20 + uu) * 16 + s16]);
                    float ai = sigm_(gi), af = sigm_(gf);
                    float ag = tanha_(ga), ao = sigm_(go);
                    float cn = fmaf(af, cs[jj], ai * ag);
                    cs[jj] = cn;
                    float hv = ao * tanhx_(cn);
                    hd[uu * 16 + s16] = pk2(hv, hv);
                }
            }
        }
        PBAR(P);

        // stage next x tile when M is about to cross into it
        if (((t + 1) & 15) == 0 && (t + 1) < Tlen) {
            int sq = lt & 15, tt = lt >> 4;
            int bb = sbase + sq;
            const float* xrow = x + (size_t)((bb < Btot) ? bb : (Btot - 1)) * Tlen;
            int tg = t + 1 + tt;
            xt_tile[tt * 16 + sq] = (tg < Tlen && bb < Btot) ? __ldg(&xrow[tg]) : 0.f;
            PBAR(P);
        }

        // ================= PHASE M =================
        if (isG1) {
            // gates1(t) from {h0(t), h1(t-1)}
            u64 a[5];
            #pragma unroll
            for (int k = 0; k < 5; ++k) a[k] = bp[k];
            #pragma unroll
            for (int m2 = 0; m2 < 10; ++m2) {
                u64 h2a = h0[(2 * m2) * 16 + s16];
                u64 h2b = h0[(2 * m2 + 1) * 16 + s16];
                #pragma unroll
                for (int k = 0; k < 5; ++k) {
                    ulonglong2 wu = *reinterpret_cast<const ulonglong2*>(&w1s[(pb + k) * 40 + 2 * m2]);
                    a[k] = fma2(wu.x, h2a, a[k]);
                    a[k] = fma2(wu.y, h2b, a[k]);
                }
            }
            #pragma unroll
            for (int m2 = 0; m2 < 10; ++m2) {
                u64 h2a = h1[(2 * m2) * 16 + s16];
                u64 h2b = h1[(2 * m2 + 1) * 16 + s16];
                #pragma unroll
                for (int k = 0; k < 5; ++k) {
                    ulonglong2 wv = *reinterpret_cast<const ulonglong2*>(&w1s[(pb + k) * 40 + 20 + 2 * m2]);
                    a[k] = fma2(wv.x, h2a, a[k]);
                    a[k] = fma2(wv.y, h2b, a[k]);
                }
            }
            #pragma unroll
            for (int k = 0; k < 5; ++k) g1[(pb + k) * 16 + s16] = a[k];
        } else {
            // gates0(t+1) from {x(t+1), h0(t)}
            float xv = (t + 1 < Tlen) ? xt_tile[((t + 1) & 15) * 16 + s16] : 0.f;
            u64 xv2 = pk2(xv, xv);
            u64 a[5];
            #pragma unroll
            for (int k = 0; k < 5; ++k) a[k] = fma2(wxp[k], xv2, bp[k]);
            #pragma unroll
            for (int m2 = 0; m2 < 10; ++m2) {
                u64 h2a = h0[(2 * m2) * 16 + s16];
                u64 h2b = h0[(2 * m2 + 1) * 16 + s16];
                #pragma unroll
                for (int k = 0; k < 5; ++k) {
                    ulonglong2 w0 = *reinterpret_cast<const ulonglong2*>(&w0s[(pb + k) * 20 + 2 * m2]);
                    a[k] = fma2(w0.x, h2a, a[k]);
                    a[k] = fma2(w0.y, h2b, a[k]);
                }
            }
            #pragma unroll
            for (int k = 0; k < 5; ++k) g0[(pb + k) * 16 + s16] = a[k];
        }
        PBAR(P);
    }

    // ---- epilogue: cell1(T-1) -> h1(T-1), G1 warps ----
    if (isG1) {
        #pragma unroll
        for (int jj = 0; jj < 3; ++jj) {
            int uu = hwm + 8 * jj;
            if (uu < 20) {
                float gi, gf, ga, go;
                up2(gi, gf, g1[uu * 16 + s16]);
                up2(ga, go, g1[(20 + uu) * 16 + s16]);
                float ai = sigm_(gi), af = sigm_(gf);
                float ag = tanha_(ga), ao = sigm_(go);
                float cn = fmaf(af, cs[jj], ai * ag);
                cs[jj] = cn;
                float hv = ao * tanhx_(cn);
                h1[uu * 16 + s16] = pk2(hv, hv);
            }
        }
    }
    PBAR(P);

    // ---- FC head: 16 threads per pipeline ----
    if (lt < 16) {
        float acc = __ldg(&fcb[0]);
        #pragma unroll
        for (int j = 0; j < 20; ++j) {
            float lo, hi;
            up2(lo, hi, h1[j * 16 + lt]);
            acc = fmaf(__ldg(&fcW[j]), lo, acc);
        }
        int bo = sbase + lt;
        if (bo < Btot) out[bo] = acc;
    }
}

extern "C" void kernel_launch(void* const* d_in, const int* in_sizes, int n_in,
                              void* d_out, int out_size)
{
    const float* x    = (const float*)d_in[0];
    const float* Wih0 = (const float*)d_in[1];
    const float* Whh0 = (const float*)d_in[2];
    const float* bih0 = (const float*)d_in[3];
    const float* bhh0 = (const float*)d_in[4];
    const float* Wih1 = (const float*)d_in[5];
    const float* Whh1 = (const float*)d_in[6];
    const float* bih1 = (const float*)d_in[7];
    const float* bhh1 = (const float*)d_in[8];
    const float* fcW  = (const float*)d_in[9];
    const float* fcb  = (const float*)d_in[10];

    const int B = out_size;              // out is [B, 1] fp32
    const int T = in_sizes[0] / B;       // x is [B, T, 1]
    const int blocks = (B + 31) / 32;    // 32 seqs per 512-thread block

    lstm2_fc_kernel<<<blocks, 512>>>(x, Wih0, Whh0, bih0, bhh0,
                                     Wih1, Whh1, bih1, bhh1,
                                     fcW, fcb, (float*)d_out, B, T);
}

// round 13
// speedup vs baseline: 1.3921x; 1.3921x over previous
#include <cuda_runtime.h>
#include <cstddef>

// 2-layer LSTM (H=20) + FC head, B=4096, T=512, D=1.
// 256-thread block, 8 warps, lane = sequence (32 seqs/block, grid 128).
// Warp w<4: layer1 units w*5..w*5+4 ; warp w>=4: layer0 units (w-4)*5.. .
// Each warp computes ALL 4 gates (10 pair accumulators) for its units, then
// the cell inline in registers -> gates never hit shared; ONE barrier/step.
// h and x tiles double-buffered. Software pipeline: iter k runs layer0 step k
// and layer1 step k-1.

using u64 = unsigned long long;

__device__ __forceinline__ u64 fma2(u64 a, u64 b, u64 c) {
    u64 d;
    asm("fma.rn.f32x2 %0, %1, %2, %3;" : "=l"(d) : "l"(a), "l"(b), "l"(c));
    return d;
}
__device__ __forceinline__ u64 pk2(float lo, float hi) {
    u64 r;
    asm("mov.b64 %0, {%1, %2};" : "=l"(r) : "f"(lo), "f"(hi));
    return r;
}
__device__ __forceinline__ void up2(float& lo, float& hi, u64 v) {
    asm("mov.b64 {%0, %1}, %2;" : "=f"(lo), "=f"(hi) : "l"(v));
}
__device__ __forceinline__ float ex2_(float x) {
    float y; asm("ex2.approx.f32 %0, %1;" : "=f"(y) : "f"(x)); return y;
}
__device__ __forceinline__ float rcp_(float x) {
    float y; asm("rcp.approx.f32 %0, %1;" : "=f"(y) : "f"(x)); return y;
}

#define L2E 1.4426950408889634f

__device__ __forceinline__ float sigm_(float x) {
    return rcp_(1.0f + ex2_(-L2E * x));
}
__device__ __forceinline__ float tanhx_(float x) {
    return fmaf(2.0f, rcp_(1.0f + ex2_(-2.0f * L2E * x)), -1.0f);
}

// pair p in [0,40): p<20 -> rows (p, 20+p) = (i,f) of unit p
//                   p>=20 -> rows (40+j, 60+j) = (g,o) of unit j=p-20
__global__ void __launch_bounds__(256, 1) lstm2_fc_kernel(
    const float* __restrict__ x,     // [B, T]
    const float* __restrict__ Wih0,  // [80, 1]
    const float* __restrict__ Whh0,  // [80, 20]
    const float* __restrict__ bih0,  // [80]
    const float* __restrict__ bhh0,  // [80]
    const float* __restrict__ Wih1,  // [80, 20]
    const float* __restrict__ Whh1,  // [80, 20]
    const float* __restrict__ bih1,  // [80]
    const float* __restrict__ bhh1,  // [80]
    const float* __restrict__ fcW,   // [1, 20]
    const float* __restrict__ fcb,   // [1]
    float* __restrict__ out,         // [B, 1]
    int Btot, int Tlen)
{
    __shared__ __align__(16) u64 w0s[40 * 20];    // pair-packed Whh0
    __shared__ __align__(16) u64 w1s[40 * 40];    // pair-packed [Wih1 | Whh1]
    __shared__ __align__(16) float h0d[2][20 * 32];  // double-buffered h0
    __shared__ __align__(16) float h1d[2][20 * 32];  // double-buffered h1
    __shared__ __align__(16) float xsd[2][16 * 32];  // double-buffered x tiles

    const int tid = threadIdx.x;

    // ---- pack weights (pair layout) ----
    for (int idx = tid; idx < 800; idx += 256) {
        int p = idx / 20, m = idx % 20;
        int j = (p < 20) ? p : (p - 20);
        int rlo = (p < 20) ? j : (40 + j);
        int rhi = rlo + 20;
        w0s[p * 20 + m] = pk2(Whh0[rlo * 20 + m], Whh0[rhi * 20 + m]);
    }
    for (int idx = tid; idx < 1600; idx += 256) {
        int p = idx / 40, mm = idx % 40;
        int j = (p < 20) ? p : (p - 20);
        int rlo = (p < 20) ? j : (40 + j);
        int rhi = rlo + 20;
        const float* mat = (mm < 20) ? Wih1 : Whh1;
        int m = (mm < 20) ? mm : (mm - 20);
        w1s[p * 40 + mm] = pk2(mat[rlo * 20 + m], mat[rhi * 20 + m]);
    }
    for (int idx = tid; idx < 1280; idx += 256) {
        h0d[0][idx % 640] = 0.f; h0d[1][idx % 640] = 0.f;
        h1d[0][idx % 640] = 0.f; h1d[1][idx % 640] = 0.f;
    }

    const int w = tid >> 5;         // warp 0..7
    const int s = tid & 31;         // lane = sequence
    const bool isG1 = (w < 4);      // layer1 warps
    const int j0 = (w & 3) * 5;     // first owned unit
    const int b0g = blockIdx.x * 32;

    // ---- stage x tile 0 ----
    {
        int sq = tid & 31, tt2 = tid >> 5;
        int bb = b0g + sq;
        const float* xrow = x + (size_t)((bb < Btot) ? bb : (Btot - 1)) * Tlen;
        #pragma unroll
        for (int ii = 0; ii < 2; ++ii) {
            int tt = tt2 * 2 + ii;
            xsd[0][tt * 32 + sq] = (tt < Tlen && bb < Btot) ? __ldg(&xrow[tt]) : 0.f;
        }
    }

    // per-warp pair constants (uniform across lanes): i<5 -> IF pair of unit
    // j0+i ; i>=5 -> GO pair of unit j0+i-5.
    u64 cst[10], wx[10];
    #pragma unroll
    for (int i = 0; i < 10; ++i) {
        int pp = (i < 5) ? (j0 + i) : (15 + j0 + i);
        int j = (pp < 20) ? pp : (pp - 20);
        int rlo = (pp < 20) ? j : (40 + j);
        int rhi = rlo + 20;
        if (isG1) {
            cst[i] = pk2(__ldg(&bih1[rlo]) + __ldg(&bhh1[rlo]),
                         __ldg(&bih1[rhi]) + __ldg(&bhh1[rhi]));
            wx[i] = 0ull;
        } else {
            cst[i] = pk2(__ldg(&bih0[rlo]) + __ldg(&bhh0[rlo]),
                         __ldg(&bih0[rhi]) + __ldg(&bhh0[rhi]));
            wx[i] = pk2(__ldg(&Wih0[rlo]), __ldg(&Wih0[rhi]));
        }
    }

    __syncthreads();

    float cs[5] = {0.f, 0.f, 0.f, 0.f, 0.f};   // c for owned units

    #pragma unroll 1
    for (int k = 0; k <= Tlen; ++k) {
        if (!isG1) {
            // ======== layer0, step k ========
            if (k < Tlen) {
                float xv = xsd[(k >> 4) & 1][(k & 15) * 32 + s];
                u64 x2 = pk2(xv, xv);
                u64 acc[10];
                #pragma unroll
                for (int i = 0; i < 10; ++i) acc[i] = fma2(wx[i], x2, cst[i]);
                const float* hp = &h0d[(k + 1) & 1][0];   // h0(k-1)
                #pragma unroll
                for (int m2 = 0; m2 < 10; ++m2) {
                    float ha = hp[(2 * m2) * 32 + s];
                    float hb = hp[(2 * m2 + 1) * 32 + s];
                    u64 h2a = pk2(ha, ha), h2b = pk2(hb, hb);
                    #pragma unroll
                    for (int i = 0; i < 10; ++i) {
                        int pp = (i < 5) ? (j0 + i) : (15 + j0 + i);
                        ulonglong2 wv = *reinterpret_cast<const ulonglong2*>(&w0s[pp * 20 + 2 * m2]);
                        acc[i] = fma2(wv.x, h2a, acc[i]);
                        acc[i] = fma2(wv.y, h2b, acc[i]);
                    }
                }
                float* hw = &h0d[k & 1][0];               // h0(k)
                #pragma unroll
                for (int jl = 0; jl < 5; ++jl) {
                    float gi, gf, gg, go;
                    up2(gi, gf, acc[jl]);
                    up2(gg, go, acc[5 + jl]);
                    float ai = sigm_(gi), af = sigm_(gf);
                    float ag = tanhx_(gg), ao = sigm_(go);
                    float cn = fmaf(af, cs[jl], ai * ag);
                    cs[jl] = cn;
                    hw[(j0 + jl) * 32 + s] = ao * tanhx_(cn);
                }
            }
        } else if (k >= 1) {
            // ======== layer1, step k-1 ========
            u64 acc[10];
            #pragma unroll
            for (int i = 0; i < 10; ++i) acc[i] = cst[i];
            const float* hp0 = &h0d[(k + 1) & 1][0];      // h0(k-1)
            const float* hp1 = &h1d[k & 1][0];            // h1(k-2)
            #pragma unroll
            for (int m2 = 0; m2 < 10; ++m2) {
                float ha0 = hp0[(2 * m2) * 32 + s];
                float hb0 = hp0[(2 * m2 + 1) * 32 + s];
                float ha1 = hp1[(2 * m2) * 32 + s];
                float hb1 = hp1[(2 * m2 + 1) * 32 + s];
                u64 h2a0 = pk2(ha0, ha0), h2b0 = pk2(hb0, hb0);
                u64 h2a1 = pk2(ha1, ha1), h2b1 = pk2(hb1, hb1);
                #pragma unroll
                for (int i = 0; i < 10; ++i) {
                    int pp = (i < 5) ? (j0 + i) : (15 + j0 + i);
                    ulonglong2 wu = *reinterpret_cast<const ulonglong2*>(&w1s[pp * 40 + 2 * m2]);
                    ulonglong2 wv = *reinterpret_cast<const ulonglong2*>(&w1s[pp * 40 + 20 + 2 * m2]);
                    acc[i] = fma2(wu.x, h2a0, acc[i]);
                    acc[i] = fma2(wu.y, h2b0, acc[i]);
                    acc[i] = fma2(wv.x, h2a1, acc[i]);
                    acc[i] = fma2(wv.y, h2b1, acc[i]);
                }
            }
            float* hw = &h1d[(k + 1) & 1][0];             // h1(k-1)
            #pragma unroll
            for (int jl = 0; jl < 5; ++jl) {
                float gi, gf, gg, go;
                up2(gi, gf, acc[jl]);
                up2(gg, go, acc[5 + jl]);
                float ai = sigm_(gi), af = sigm_(gf);
                float ag = tanhx_(gg), ao = sigm_(go);
                float cn = fmaf(af, cs[jl], ai * ag);
                cs[jl] = cn;
                hw[(j0 + jl) * 32 + s] = ao * tanhx_(cn);
            }
        }

        // stage next x tile (read only after the barrier; opposite parity)
        if ((k & 15) == 15 && (k + 1) < Tlen) {
            float* xd = xsd[((k + 1) >> 4) & 1];
            int sq = tid & 31, tt2 = tid >> 5;
            int bb = b0g + sq;
            const float* xrow = x + (size_t)((bb < Btot) ? bb : (Btot - 1)) * Tlen;
            #pragma unroll
            for (int ii = 0; ii < 2; ++ii) {
                int tt = tt2 * 2 + ii;
                int tg = k + 1 + tt;
                xd[tt * 32 + sq] = (tg < Tlen && bb < Btot) ? __ldg(&xrow[tg]) : 0.f;
            }
        }
        __syncthreads();
    }

    // ---- FC head: h1(T-1) lives in h1d[(Tlen-1)&1] ----
    if (tid < 32) {
        const float* hf = &h1d[(Tlen - 1) & 1][0];
        float acc = __ldg(&fcb[0]);
        #pragma unroll
        for (int j = 0; j < 20; ++j)
            acc = fmaf(__ldg(&fcW[j]), hf[j * 32 + tid], acc);
        int bo = b0g + tid;
        if (bo < Btot) out[bo] = acc;
    }
}

extern "C" void kernel_launch(void* const* d_in, const int* in_sizes, int n_in,
                              void* d_out, int out_size)
{
    const float* x    = (const float*)d_in[0];
    const float* Wih0 = (const float*)d_in[1];
    const float* Whh0 = (const float*)d_in[2];
    const float* bih0 = (const float*)d_in[3];
    const float* bhh0 = (const float*)d_in[4];
    const float* Wih1 = (const float*)d_in[5];
    const float* Whh1 = (const float*)d_in[6];
    const float* bih1 = (const float*)d_in[7];
    const float* bhh1 = (const float*)d_in[8];
    const float* fcW  = (const float*)d_in[9];
    const float* fcb  = (const float*)d_in[10];

    const int B = out_size;              // out is [B, 1] fp32
    const int T = in_sizes[0] / B;       // x is [B, T, 1]
    const int blocks = (B + 31) / 32;    // 32 seqs per 256-thread block

    lstm2_fc_kernel<<<blocks, 256>>>(x, Wih0, Whh0, bih0, bhh0,
                                     Wih1, Whh1, bih1, bhh1,
                                     fcW, fcb, (float*)d_out, B, T);
}

// round 14
// speedup vs baseline: 1.3942x; 1.0015x over previous
#include <cuda_runtime.h>
#include <cstddef>

// 2-layer LSTM (H=20) + FC head, B=4096, T=512, D=1.
// 256-thread block, 8 warps, lane = sequence (32 seqs/block, grid 128).
// Warp w<4: layer1 units w*5..w*5+4 ; warp w>=4: layer0 units (w-4)*5.. .
// Each warp computes ALL 4 gates (10 pair accumulators) for its units, then
// the cell inline in registers -> gates never hit shared; ONE barrier/step.
// h and x tiles double-buffered. Software pipeline: iter k runs layer0 step k
// and layer1 step k-1.

using u64 = unsigned long long;

__device__ __forceinline__ u64 fma2(u64 a, u64 b, u64 c) {
    u64 d;
    asm("fma.rn.f32x2 %0, %1, %2, %3;" : "=l"(d) : "l"(a), "l"(b), "l"(c));
    return d;
}
__device__ __forceinline__ u64 pk2(float lo, float hi) {
    u64 r;
    asm("mov.b64 %0, {%1, %2};" : "=l"(r) : "f"(lo), "f"(hi));
    return r;
}
__device__ __forceinline__ void up2(float& lo, float& hi, u64 v) {
    asm("mov.b64 {%0, %1}, %2;" : "=f"(lo), "=f"(hi) : "l"(v));
}
__device__ __forceinline__ float ex2_(float x) {
    float y; asm("ex2.approx.f32 %0, %1;" : "=f"(y) : "f"(x)); return y;
}
__device__ __forceinline__ float rcp_(float x) {
    float y; asm("rcp.approx.f32 %0, %1;" : "=f"(y) : "f"(x)); return y;
}

#define L2E 1.4426950408889634f

__device__ __forceinline__ float sigm_(float x) {
    return rcp_(1.0f + ex2_(-L2E * x));
}
__device__ __forceinline__ float tanhx_(float x) {
    return fmaf(2.0f, rcp_(1.0f + ex2_(-2.0f * L2E * x)), -1.0f);
}

// pair p in [0,40): p<20 -> rows (p, 20+p) = (i,f) of unit p
//                   p>=20 -> rows (40+j, 60+j) = (g,o) of unit j=p-20
__global__ void __launch_bounds__(256, 1) lstm2_fc_kernel(
    const float* __restrict__ x,     // [B, T]
    const float* __restrict__ Wih0,  // [80, 1]
    const float* __restrict__ Whh0,  // [80, 20]
    const float* __restrict__ bih0,  // [80]
    const float* __restrict__ bhh0,  // [80]
    const float* __restrict__ Wih1,  // [80, 20]
    const float* __restrict__ Whh1,  // [80, 20]
    const float* __restrict__ bih1,  // [80]
    const float* __restrict__ bhh1,  // [80]
    const float* __restrict__ fcW,   // [1, 20]
    const float* __restrict__ fcb,   // [1]
    float* __restrict__ out,         // [B, 1]
    int Btot, int Tlen)
{
    __shared__ __align__(16) u64 w0s[40 * 20];    // pair-packed Whh0
    __shared__ __align__(16) u64 w1s[40 * 40];    // pair-packed [Wih1 | Whh1]
    __shared__ __align__(16) float h0d[2][20 * 32];  // double-buffered h0
    __shared__ __align__(16) float h1d[2][20 * 32];  // double-buffered h1
    __shared__ __align__(16) float xsd[2][16 * 32];  // double-buffered x tiles

    const int tid = threadIdx.x;

    // ---- pack weights (pair layout) ----
    for (int idx = tid; idx < 800; idx += 256) {
        int p = idx / 20, m = idx % 20;
        int j = (p < 20) ? p : (p - 20);
        int rlo = (p < 20) ? j : (40 + j);
        int rhi = rlo + 20;
        w0s[p * 20 + m] = pk2(Whh0[rlo * 20 + m], Whh0[rhi * 20 + m]);
    }
    for (int idx = tid; idx < 1600; idx += 256) {
        int p = idx / 40, mm = idx % 40;
        int j = (p < 20) ? p : (p - 20);
        int rlo = (p < 20) ? j : (40 + j);
        int rhi = rlo + 20;
        const float* mat = (mm < 20) ? Wih1 : Whh1;
        int m = (mm < 20) ? mm : (mm - 20);
        w1s[p * 40 + mm] = pk2(mat[rlo * 20 + m], mat[rhi * 20 + m]);
    }
    for (int idx = tid; idx < 1280; idx += 256) {
        h0d[0][idx % 640] = 0.f; h0d[1][idx % 640] = 0.f;
        h1d[0][idx % 640] = 0.f; h1d[1][idx % 640] = 0.f;
    }

    const int w = tid >> 5;         // warp 0..7
    const int s = tid & 31;         // lane = sequence
    const bool isG1 = (w < 4);      // layer1 warps
    const int j0 = (w & 3) * 5;     // first owned unit
    const int b0g = blockIdx.x * 32;

    // ---- stage x tile 0 ----
    {
        int sq = tid & 31, tt2 = tid >> 5;
        int bb = b0g + sq;
        const float* xrow = x + (size_t)((bb < Btot) ? bb : (Btot - 1)) * Tlen;
        #pragma unroll
        for (int ii = 0; ii < 2; ++ii) {
            int tt = tt2 * 2 + ii;
            xsd[0][tt * 32 + sq] = (tt < Tlen && bb < Btot) ? __ldg(&xrow[tt]) : 0.f;
        }
    }

    // per-warp pair constants (uniform across lanes): i<5 -> IF pair of unit
    // j0+i ; i>=5 -> GO pair of unit j0+i-5.
    u64 cst[10], wx[10];
    #pragma unroll
    for (int i = 0; i < 10; ++i) {
        int pp = (i < 5) ? (j0 + i) : (15 + j0 + i);
        int j = (pp < 20) ? pp : (pp - 20);
        int rlo = (pp < 20) ? j : (40 + j);
        int rhi = rlo + 20;
        if (isG1) {
            cst[i] = pk2(__ldg(&bih1[rlo]) + __ldg(&bhh1[rlo]),
                         __ldg(&bih1[rhi]) + __ldg(&bhh1[rhi]));
            wx[i] = 0ull;
        } else {
            cst[i] = pk2(__ldg(&bih0[rlo]) + __ldg(&bhh0[rlo]),
                         __ldg(&bih0[rhi]) + __ldg(&bhh0[rhi]));
            wx[i] = pk2(__ldg(&Wih0[rlo]), __ldg(&Wih0[rhi]));
        }
    }

    __syncthreads();

    float cs[5] = {0.f, 0.f, 0.f, 0.f, 0.f};   // c for owned units

    #pragma unroll 1
    for (int k = 0; k <= Tlen; ++k) {
        if (!isG1) {
            // ======== layer0, step k ========
            if (k < Tlen) {
                float xv = xsd[(k >> 4) & 1][(k & 15) * 32 + s];
                u64 x2 = pk2(xv, xv);
                u64 acc[10];
                #pragma unroll
                for (int i = 0; i < 10; ++i) acc[i] = fma2(wx[i], x2, cst[i]);
                const float* hp = &h0d[(k + 1) & 1][0];   // h0(k-1)
                #pragma unroll
                for (int m2 = 0; m2 < 10; ++m2) {
                    float ha = hp[(2 * m2) * 32 + s];
                    float hb = hp[(2 * m2 + 1) * 32 + s];
                    u64 h2a = pk2(ha, ha), h2b = pk2(hb, hb);
                    #pragma unroll
                    for (int i = 0; i < 10; ++i) {
                        int pp = (i < 5) ? (j0 + i) : (15 + j0 + i);
                        ulonglong2 wv = *reinterpret_cast<const ulonglong2*>(&w0s[pp * 20 + 2 * m2]);
                        acc[i] = fma2(wv.x, h2a, acc[i]);
                        acc[i] = fma2(wv.y, h2b, acc[i]);
                    }
                }
                float* hw = &h0d[k & 1][0];               // h0(k)
                #pragma unroll
                for (int jl = 0; jl < 5; ++jl) {
                    float gi, gf, gg, go;
                    up2(gi, gf, acc[jl]);
                    up2(gg, go, acc[5 + jl]);
                    float ai = sigm_(gi), af = sigm_(gf);
                    float ag = tanhx_(gg), ao = sigm_(go);
                    float cn = fmaf(af, cs[jl], ai * ag);
                    cs[jl] = cn;
                    hw[(j0 + jl) * 32 + s] = ao * tanhx_(cn);
                }
            }
        } else if (k >= 1) {
            // ======== layer1, step k-1 ========
            u64 acc[10];
            #pragma unroll
            for (int i = 0; i < 10; ++i) acc[i] = cst[i];
            const float* hp0 = &h0d[(k + 1) & 1][0];      // h0(k-1)
            const float* hp1 = &h1d[k & 1][0];            // h1(k-2)
            #pragma unroll
            for (int m2 = 0; m2 < 10; ++m2) {
                float ha0 = hp0[(2 * m2) * 32 + s];
                float hb0 = hp0[(2 * m2 + 1) * 32 + s];
                float ha1 = hp1[(2 * m2) * 32 + s];
                float hb1 = hp1[(2 * m2 + 1) * 32 + s];
                u64 h2a0 = pk2(ha0, ha0), h2b0 = pk2(hb0, hb0);
                u64 h2a1 = pk2(ha1, ha1), h2b1 = pk2(hb1, hb1);
                #pragma unroll
                for (int i = 0; i < 10; ++i) {
                    int pp = (i < 5) ? (j0 + i) : (15 + j0 + i);
                    ulonglong2 wu = *reinterpret_cast<const ulonglong2*>(&w1s[pp * 40 + 2 * m2]);
                    ulonglong2 wv = *reinterpret_cast<const ulonglong2*>(&w1s[pp * 40 + 20 + 2 * m2]);
                    acc[i] = fma2(wu.x, h2a0, acc[i]);
                    acc[i] = fma2(wu.y, h2b0, acc[i]);
                    acc[i] = fma2(wv.x, h2a1, acc[i]);
                    acc[i] = fma2(wv.y, h2b1, acc[i]);
                }
            }
            float* hw = &h1d[(k + 1) & 1][0];             // h1(k-1)
            #pragma unroll
            for (int jl = 0; jl < 5; ++jl) {
                float gi, gf, gg, go;
                up2(gi, gf, acc[jl]);
                up2(gg, go, acc[5 + jl]);
                float ai = sigm_(gi), af = sigm_(gf);
                float ag = tanhx_(gg), ao = sigm_(go);
                float cn = fmaf(af, cs[jl], ai * ag);
                cs[jl] = cn;
                hw[(j0 + jl) * 32 + s] = ao * tanhx_(cn);
            }
        }

        // stage next x tile (read only after the barrier; opposite parity)
        if ((k & 15) == 15 && (k + 1) < Tlen) {
            float* xd = xsd[((k + 1) >> 4) & 1];
            int sq = tid & 31, tt2 = tid >> 5;
            int bb = b0g + sq;
            const float* xrow = x + (size_t)((bb < Btot) ? bb : (Btot - 1)) * Tlen;
            #pragma unroll
            for (int ii = 0; ii < 2; ++ii) {
                int tt = tt2 * 2 + ii;
                int tg = k + 1 + tt;
                xd[tt * 32 + sq] = (tg < Tlen && bb < Btot) ? __ldg(&xrow[tg]) : 0.f;
            }
        }
        __syncthreads();
    }

    // ---- FC head: h1(T-1) lives in h1d[(Tlen-1)&1] ----
    if (tid < 32) {
        const float* hf = &h1d[(Tlen - 1) & 1][0];
        float acc = __ldg(&fcb[0]);
        #pragma unroll
        for (int j = 0; j < 20; ++j)
            acc = fmaf(__ldg(&fcW[j]), hf[j * 32 + tid], acc);
        int bo = b0g + tid;
        if (bo < Btot) out[bo] = acc;
    }
}

extern "C" void kernel_launch(void* const* d_in, const int* in_sizes, int n_in,
                              void* d_out, int out_size)
{
    const float* x    = (const float*)d_in[0];
    const float* Wih0 = (const float*)d_in[1];
    const float* Whh0 = (const float*)d_in[2];
    const float* bih0 = (const float*)d_in[3];
    const float* bhh0 = (const float*)d_in[4];
    const float* Wih1 = (const float*)d_in[5];
    const float* Whh1 = (const float*)d_in[6];
    const float* bih1 = (const float*)d_in[7];
    const float* bhh1 = (const float*)d_in[8];
    const float* fcW  = (const float*)d_in[9];
    const float* fcb  = (const float*)d_in[10];

    const int B = out_size;              // out is [B, 1] fp32
    const int T = in_sizes[0] / B;       // x is [B, T, 1]
    const int blocks = (B + 31) / 32;    // 32 seqs per 256-thread block

    lstm2_fc_kernel<<<blocks, 256>>>(x, Wih0, Whh0, bih0, bhh0,
                                     Wih1, Whh1, bih1, bhh1,
                                     fcW, fcb, (float*)d_out, B, T);
}

// round 15
// speedup vs baseline: 1.4367x; 1.0305x over previous
#include <cuda_runtime.h>
#include <cstddef>

// 2-layer LSTM (H=20) + FC head, B=4096, T=512, D=1.
// 256 threads, lane = sequence (32 seqs/block, grid 128).
// DECOUPLED layer groups with named-barrier producer/consumer rings:
//   warps 4-7 (L0): step loop k, write h0(k) -> h0b[k&3], bar.arrive R[k&3]
//   warps 0-3 (L1): step loop j, bar.sync R[j&3], read h0(j), bar.arrive C[j&3]
//   L0 syncs C[k&3] (k>=4) before overwriting slot; internal bar 9 for k<4.
// Gates stay in registers (R13). h float, x double-buffered, h0 4-deep ring.

using u64 = unsigned long long;

__device__ __forceinline__ u64 fma2(u64 a, u64 b, u64 c) {
    u64 d;
    asm("fma.rn.f32x2 %0, %1, %2, %3;" : "=l"(d) : "l"(a), "l"(b), "l"(c));
    return d;
}
__device__ __forceinline__ u64 pk2(float lo, float hi) {
    u64 r;
    asm("mov.b64 %0, {%1, %2};" : "=l"(r) : "f"(lo), "f"(hi));
    return r;
}
__device__ __forceinline__ void up2(float& lo, float& hi, u64 v) {
    asm("mov.b64 {%0, %1}, %2;" : "=f"(lo), "=f"(hi) : "l"(v));
}
__device__ __forceinline__ float ex2_(float x) {
    float y; asm("ex2.approx.f32 %0, %1;" : "=f"(y) : "f"(x)); return y;
}
__device__ __forceinline__ float rcp_(float x) {
    float y; asm("rcp.approx.f32 %0, %1;" : "=f"(y) : "f"(x)); return y;
}

#define L2E 1.4426950408889634f

__device__ __forceinline__ float sigm_(float x) {
    return rcp_(1.0f + ex2_(-L2E * x));
}
__device__ __forceinline__ float tanhx_(float x) {
    return fmaf(2.0f, rcp_(1.0f + ex2_(-2.0f * L2E * x)), -1.0f);
}

#define BSYNC256(id)  asm volatile("bar.sync %0, 256;"   :: "r"(id) : "memory")
#define BSYNC128(id)  asm volatile("bar.sync %0, 128;"   :: "r"(id) : "memory")
#define BARRIVE256(id) asm volatile("bar.arrive %0, 256;" :: "r"(id) : "memory")

// pair p in [0,40): p<20 -> rows (p, 20+p) = (i,f) of unit p
//                   p>=20 -> rows (40+j, 60+j) = (g,o) of unit j=p-20
__global__ void __launch_bounds__(256, 1) lstm2_fc_kernel(
    const float* __restrict__ x,     // [B, T]
    const float* __restrict__ Wih0,  // [80, 1]
    const float* __restrict__ Whh0,  // [80, 20]
    const float* __restrict__ bih0,  // [80]
    const float* __restrict__ bhh0,  // [80]
    const float* __restrict__ Wih1,  // [80, 20]
    const float* __restrict__ Whh1,  // [80, 20]
    const float* __restrict__ bih1,  // [80]
    const float* __restrict__ bhh1,  // [80]
    const float* __restrict__ fcW,   // [1, 20]
    const float* __restrict__ fcb,   // [1]
    float* __restrict__ out,         // [B, 1]
    int Btot, int Tlen)
{
    __shared__ __align__(16) u64 w0s[40 * 20];       // pair-packed Whh0
    __shared__ __align__(16) u64 w1s[40 * 40];       // pair-packed [Wih1 | Whh1]
    __shared__ __align__(16) float h0b[4][20 * 32];  // 4-deep h0 ring
    __shared__ __align__(16) float h1b[2][20 * 32];  // double-buffered h1
    __shared__ __align__(16) float xsd[2][16 * 32];  // double-buffered x tiles

    const int tid = threadIdx.x;

    // ---- pack weights (pair layout) ----
    for (int idx = tid; idx < 800; idx += 256) {
        int p = idx / 20, m = idx % 20;
        int j = (p < 20) ? p : (p - 20);
        int rlo = (p < 20) ? j : (40 + j);
        int rhi = rlo + 20;
        w0s[p * 20 + m] = pk2(Whh0[rlo * 20 + m], Whh0[rhi * 20 + m]);
    }
    for (int idx = tid; idx < 1600; idx += 256) {
        int p = idx / 40, mm = idx % 40;
        int j = (p < 20) ? p : (p - 20);
        int rlo = (p < 20) ? j : (40 + j);
        int rhi = rlo + 20;
        const float* mat = (mm < 20) ? Wih1 : Whh1;
        int m = (mm < 20) ? mm : (mm - 20);
        w1s[p * 40 + mm] = pk2(mat[rlo * 20 + m], mat[rhi * 20 + m]);
    }
    for (int idx = tid; idx < 4 * 640; idx += 256) h0b[idx / 640][idx % 640] = 0.f;
    for (int idx = tid; idx < 2 * 640; idx += 256) h1b[idx / 640][idx % 640] = 0.f;

    const int w = tid >> 5;         // warp 0..7
    const int s = tid & 31;         // lane = sequence
    const bool isG1 = (w < 4);      // layer-1 group
    const int j0 = (w & 3) * 5;     // first owned unit
    const int b0g = blockIdx.x * 32;

    // ---- stage x tile 0 (all 256 threads) ----
    {
        int sq = tid & 31, tt2 = tid >> 5;
        int bb = b0g + sq;
        const float* xrow = x + (size_t)((bb < Btot) ? bb : (Btot - 1)) * Tlen;
        #pragma unroll
        for (int ii = 0; ii < 2; ++ii) {
            int tt = tt2 * 2 + ii;
            xsd[0][tt * 32 + sq] = (tt < Tlen && bb < Btot) ? __ldg(&xrow[tt]) : 0.f;
        }
    }

    // per-warp pair constants (uniform across lanes)
    u64 cst[10], wx[10];
    #pragma unroll
    for (int i = 0; i < 10; ++i) {
        int pp = (i < 5) ? (j0 + i) : (15 + j0 + i);
        int j = (pp < 20) ? pp : (pp - 20);
        int rlo = (pp < 20) ? j : (40 + j);
        int rhi = rlo + 20;
        if (isG1) {
            cst[i] = pk2(__ldg(&bih1[rlo]) + __ldg(&bhh1[rlo]),
                         __ldg(&bih1[rhi]) + __ldg(&bhh1[rhi]));
            wx[i] = 0ull;
        } else {
            cst[i] = pk2(__ldg(&bih0[rlo]) + __ldg(&bhh0[rlo]),
                         __ldg(&bih0[rhi]) + __ldg(&bhh0[rhi]));
            wx[i] = pk2(__ldg(&Wih0[rlo]), __ldg(&Wih0[rhi]));
        }
    }

    __syncthreads();

    float cs[5] = {0.f, 0.f, 0.f, 0.f, 0.f};

    if (isG1) {
        // ========== layer-1 group: steps j = 0..T-1 ==========
        #pragma unroll 1
        for (int j = 0; j < Tlen; ++j) {
            BSYNC256(1 + (j & 3));                 // h0(j) ready (+ L1 internal sync)
            const float* hp0 = h0b[j & 3];         // h0(j)
            const float* hp1 = h1b[(j + 1) & 1];   // h1(j-1)
            u64 acc[10];
            #pragma unroll
            for (int i = 0; i < 10; ++i) acc[i] = cst[i];
            #pragma unroll
            for (int m2 = 0; m2 < 10; ++m2) {
                float a0 = hp0[(2 * m2) * 32 + s];
                float b0 = hp0[(2 * m2 + 1) * 32 + s];
                float a1 = hp1[(2 * m2) * 32 + s];
                float b1 = hp1[(2 * m2 + 1) * 32 + s];
                u64 h2a0 = pk2(a0, a0), h2b0 = pk2(b0, b0);
                u64 h2a1 = pk2(a1, a1), h2b1 = pk2(b1, b1);
                #pragma unroll
                for (int i = 0; i < 10; ++i) {
                    int pp = (i < 5) ? (j0 + i) : (15 + j0 + i);
                    ulonglong2 wu = *reinterpret_cast<const ulonglong2*>(&w1s[pp * 40 + 2 * m2]);
                    ulonglong2 wv = *reinterpret_cast<const ulonglong2*>(&w1s[pp * 40 + 20 + 2 * m2]);
                    acc[i] = fma2(wu.x, h2a0, acc[i]);
                    acc[i] = fma2(wu.y, h2b0, acc[i]);
                    acc[i] = fma2(wv.x, h2a1, acc[i]);
                    acc[i] = fma2(wv.y, h2b1, acc[i]);
                }
            }
            BARRIVE256(5 + (j & 3));               // h0(j) consumed (loads done: in-order issue)
            float* hw = h1b[j & 1];                // h1(j)
            #pragma unroll
            for (int jl = 0; jl < 5; ++jl) {
                float gi, gf, gg, go;
                up2(gi, gf, acc[jl]);
                up2(gg, go, acc[5 + jl]);
                float ai = sigm_(gi), af = sigm_(gf);
                float ag = tanhx_(gg), ao = sigm_(go);
                float cn = fmaf(af, cs[jl], ai * ag);
                cs[jl] = cn;
                hw[(j0 + jl) * 32 + s] = ao * tanhx_(cn);
            }
        }
    } else {
        // ========== layer-0 group: steps k = 0..T-1 ==========
        #pragma unroll 1
        for (int k = 0; k < Tlen; ++k) {
            if (k < 4) { BSYNC128(9); }            // L0 internal (slots still fresh)
            else       { BSYNC256(5 + (k & 3)); }  // h0(k-4) consumed (+ internal)
            float xv = xsd[(k >> 4) & 1][(k & 15) * 32 + s];
            u64 x2 = pk2(xv, xv);
            u64 acc[10];
            #pragma unroll
            for (int i = 0; i < 10; ++i) acc[i] = fma2(wx[i], x2, cst[i]);
            const float* hp = h0b[(k + 3) & 3];    // h0(k-1)
            #pragma unroll
            for (int m2 = 0; m2 < 10; ++m2) {
                float a0 = hp[(2 * m2) * 32 + s];
                float b0 = hp[(2 * m2 + 1) * 32 + s];
                u64 h2a = pk2(a0, a0), h2b = pk2(b0, b0);
                #pragma unroll
                for (int i = 0; i < 10; ++i) {
                    int pp = (i < 5) ? (j0 + i) : (15 + j0 + i);
                    ulonglong2 wv = *reinterpret_cast<const ulonglong2*>(&w0s[pp * 20 + 2 * m2]);
                    acc[i] = fma2(wv.x, h2a, acc[i]);
                    acc[i] = fma2(wv.y, h2b, acc[i]);
                }
            }
            float* hw = h0b[k & 3];                // h0(k)
            #pragma unroll
            for (int jl = 0; jl < 5; ++jl) {
                float gi, gf, gg, go;
                up2(gi, gf, acc[jl]);
                up2(gg, go, acc[5 + jl]);
                float ai = sigm_(gi), af = sigm_(gf);
                float ag = tanhx_(gg), ao = sigm_(go);
                float cn = fmaf(af, cs[jl], ai * ag);
                cs[jl] = cn;
                hw[(j0 + jl) * 32 + s] = ao * tanhx_(cn);
            }
            BARRIVE256(1 + (k & 3));               // h0(k) ready

            // stage next x tile (L0 threads only; writes the OTHER buffer)
            if ((k & 15) == 15 && (k + 1) < Tlen) {
                float* xd = xsd[((k + 1) >> 4) & 1];
                int ltid = tid & 127;
                int sq = ltid & 31, tt2 = ltid >> 5;
                int bb = b0g + sq;
                const float* xrow = x + (size_t)((bb < Btot) ? bb : (Btot - 1)) * Tlen;
                #pragma unroll
                for (int ii = 0; ii < 4; ++ii) {
                    int tt = tt2 * 4 + ii;
                    int tg = k + 1 + tt;
                    xd[tt * 32 + sq] = (tg < Tlen && bb < Btot) ? __ldg(&xrow[tg]) : 0.f;
                }
            }
        }
    }

    __syncthreads();

    // ---- FC head: h1(T-1) lives in h1b[(Tlen-1)&1] ----
    if (tid < 32) {
        const float* hf = h1b[(Tlen - 1) & 1];
        float acc = __ldg(&fcb[0]);
        #pragma unroll
        for (int j = 0; j < 20; ++j)
            acc = fmaf(__ldg(&fcW[j]), hf[j * 32 + tid], acc);
        int bo = b0g + tid;
        if (bo < Btot) out[bo] = acc;
    }
}

extern "C" void kernel_launch(void* const* d_in, const int* in_sizes, int n_in,
                              void* d_out, int out_size)
{
    const float* x    = (const float*)d_in[0];
    const float* Wih0 = (const float*)d_in[1];
    const float* Whh0 = (const float*)d_in[2];
    const float* bih0 = (const float*)d_in[3];
    const float* bhh0 = (const float*)d_in[4];
    const float* Wih1 = (const float*)d_in[5];
    const float* Whh1 = (const float*)d_in[6];
    const float* bih1 = (const float*)d_in[7];
    const float* bhh1 = (const float*)d_in[8];
    const float* fcW  = (const float*)d_in[9];
    const float* fcb  = (const float*)d_in[10];

    const int B = out_size;              // out is [B, 1] fp32
    const int T = in_sizes[0] / B;       // x is [B, T, 1]
    const int blocks = (B + 31) / 32;    // 32 seqs per 256-thread block

    lstm2_fc_kernel<<<blocks, 256>>>(x, Wih0, Whh0, bih0, bhh0,
                                     Wih1, Whh1, bih1, bhh1,
                                     fcW, fcb, (float*)d_out, B, T);
}